// round 6
// baseline (speedup 1.0000x reference)
#include <cuda_runtime.h>

#define NUM_B 2
#define NUM_H 32
#define SEQ   2048
#define HD    128
#define BM    128
#define BN    64
#define NTHREADS 256

// Grouped-tf32 smem layouts (col' = (k&3)*GROUP + (k>>2)):
#define RSK 144     // K' row stride (floats); groups of 32 padded to 36; 144 % 32 == 16
#define RSV 80      // V' row stride; groups of 16 padded to 20; 80 % 32 == 16
#define RSP 84      // P  row stride; groups of 16 padded to 20; 84 % 32 == 20
#define RAWV_STR 132  // raw V staging row stride inside V' buffer

#define KBUF (64*RSK)    // 9216 floats
#define VBUF (128*RSV)   // 10240 floats (raw 64x132=8448 fits)
#define PBUF (128*RSP)   // 10752 floats
#define SMEM_FLOATS (2*KBUF + 2*VBUF + PBUF)
#define SMEM_BYTES  (SMEM_FLOATS*4)

__device__ __forceinline__ unsigned f2tf(float x){
    unsigned r; asm("cvt.rna.tf32.f32 %0, %1;" : "=r"(r) : "f"(x)); return r;
}
__device__ __forceinline__ float f2tff(float x){
    return __uint_as_float(f2tf(x));
}
__device__ __forceinline__ float ex2f(float x){
    float r; asm("ex2.approx.f32 %0, %1;" : "=f"(r) : "f"(x)); return r;
}
__device__ __forceinline__ void mma_tf32(float c[4], const unsigned a[4],
                                         unsigned b0, unsigned b1){
    asm volatile("mma.sync.aligned.m16n8k8.row.col.f32.tf32.tf32.f32 "
                 "{%0,%1,%2,%3},{%4,%5,%6,%7},{%8,%9},{%0,%1,%2,%3};"
                 : "+f"(c[0]),"+f"(c[1]),"+f"(c[2]),"+f"(c[3])
                 : "r"(a[0]),"r"(a[1]),"r"(a[2]),"r"(a[3]),"r"(b0),"r"(b1));
}

__global__ void __launch_bounds__(NTHREADS, 1)
fa_fwd(const float* __restrict__ Q, const float* __restrict__ K,
       const float* __restrict__ V, float* __restrict__ Out)
{
    extern __shared__ float sm_[];
    float* Ks = sm_;                       // 2 buffers: raw fp32 -> converted K'
    float* Vs = sm_ + 2*KBUF;              // 2 buffers: raw fp32 -> converted V' (transposed)
    float* Ps = sm_ + 2*KBUF + 2*VBUF;     // P (tf32, grouped)

    const int tid  = threadIdx.x;
    const int warp = tid >> 5;
    const int lane = tid & 31;
    const int r0   = lane >> 2;
    const int c0   = lane & 3;

    const int qb = blockIdx.x, h = blockIdx.y, b = blockIdx.z;
    const int qbase = qb * BM;
    const size_t bh_off = ((size_t)b*NUM_H + h) * (size_t)SEQ * HD;
    const float* Qp = Q + bh_off;
    const float* Kp = K + bh_off;
    const float* Vp = V + bh_off;

    const unsigned ks_b = (unsigned)__cvta_generic_to_shared(Ks);
    const unsigned vs_b = (unsigned)__cvta_generic_to_shared(Vs);

    // 1/sqrt(128) * log2(e): layer-scaling cancels; softmax done in exp2 domain
    const float SCALE2 = 0.08838834764831845f * 1.4426950408889634f;

    // ---- Q fragments (tf32, pre-scaled) ----
    unsigned qf[16][4];
    const int qrow0 = qbase + warp*16 + r0;
    const int qrow1 = qrow0 + 8;
    #pragma unroll
    for (int kt = 0; kt < 16; kt++){
        int col = kt*8 + c0;
        qf[kt][0] = f2tf(Qp[(size_t)qrow0*HD + col]     * SCALE2);
        qf[kt][1] = f2tf(Qp[(size_t)qrow1*HD + col]     * SCALE2);
        qf[kt][2] = f2tf(Qp[(size_t)qrow0*HD + col + 4] * SCALE2);
        qf[kt][3] = f2tf(Qp[(size_t)qrow1*HD + col + 4] * SCALE2);
    }

    float o[16][4];
    #pragma unroll
    for (int i = 0; i < 16; i++){ o[i][0]=0.f; o[i][1]=0.f; o[i][2]=0.f; o[i][3]=0.f; }
    float m0 = -1e30f, m1 = -1e30f, l0 = 0.f, l1 = 0.f;

    const int jmax = 2*qb + 1;

    auto load_tiles = [&](int j, int buf){
        const float* kg = Kp + (size_t)j*BN*HD;
        const float* vg = Vp + (size_t)j*BN*HD;
        #pragma unroll
        for (int i = 0; i < 8; i++){
            int idx = tid + i*NTHREADS;
            int row = idx >> 5;
            int c4  = (idx & 31) * 4;
            unsigned ka = ks_b + (unsigned)((buf*KBUF + row*RSK + c4) * 4);
            unsigned va = vs_b + (unsigned)((buf*VBUF + row*RAWV_STR + c4) * 4);
            asm volatile("cp.async.cg.shared.global [%0], [%1], 16;"
                         :: "r"(ka), "l"(kg + (size_t)row*HD + c4));
            asm volatile("cp.async.cg.shared.global [%0], [%1], 16;"
                         :: "r"(va), "l"(vg + (size_t)row*HD + c4));
        }
        asm volatile("cp.async.commit_group;");
    };

    load_tiles(0, 0);

    for (int j = 0; j <= jmax; j++){
        const int cur = j & 1;
        asm volatile("cp.async.wait_group 0;");
        __syncthreads();                 // raw tile j visible; buf cur^1 free
        if (j < jmax) load_tiles(j + 1, cur ^ 1);

        float* Kb = Ks + cur*KBUF;
        float* Vb = Vs + cur*VBUF;

        // ===== in-place convert: raw fp32 -> grouped tf32 =====
        {
            // K: read all raw (row-major) into regs
            float4 kr[8];
            #pragma unroll
            for (int i = 0; i < 8; i++){
                int row = (tid>>5) + i*8;
                kr[i] = *(const float4*)(Kb + row*RSK + lane*4);
            }
            __syncthreads();             // all K raw reads done
            // K: write grouped: element (row, c=4*lane+e) -> [row][e*36 + lane]
            #pragma unroll
            for (int i = 0; i < 8; i++){
                int row = (tid>>5) + i*8;
                float* dst = Kb + row*RSK + lane;
                dst[0*36] = f2tff(kr[i].x);
                dst[1*36] = f2tff(kr[i].y);
                dst[2*36] = f2tff(kr[i].z);
                dst[3*36] = f2tff(kr[i].w);
            }
            // V: read all raw into regs (lane -> key row, warp -> headdim cols)
            float4 vr[8];
            #pragma unroll
            for (int i = 0; i < 8; i++){
                int rr  = lane + 32*(i & 1);
                int c4  = ((tid>>5)*4 + (i>>1)) * 4;
                vr[i] = *(const float4*)(Vb + rr*RAWV_STR + c4);
            }
            __syncthreads();             // all V raw reads done; K' complete
            // V: write transposed + grouped: (key rr, dim c) -> V'[c][(rr&3)*20 + (rr>>2)]
            #pragma unroll
            for (int i = 0; i < 8; i++){
                int rr   = lane + 32*(i & 1);
                int c4   = ((tid>>5)*4 + (i>>1)) * 4;
                int colp = (rr & 3)*20 + (rr >> 2);
                Vb[(c4+0)*RSV + colp] = f2tff(vr[i].x);
                Vb[(c4+1)*RSV + colp] = f2tff(vr[i].y);
                Vb[(c4+2)*RSV + colp] = f2tff(vr[i].z);
                Vb[(c4+3)*RSV + colp] = f2tff(vr[i].w);
            }
            __syncthreads();             // V' complete
        }

        // ===== S = Q * K^T =====
        float sacc[8][4];
        #pragma unroll
        for (int i = 0; i < 8; i++){ sacc[i][0]=0.f; sacc[i][1]=0.f; sacc[i][2]=0.f; sacc[i][3]=0.f; }

        #pragma unroll
        for (int nt = 0; nt < 8; nt++){
            const float4* kp = (const float4*)(Kb + (8*nt + r0)*RSK + c0*36);
            float4 kf[8];
            #pragma unroll
            for (int m = 0; m < 8; m++) kf[m] = kp[m];
            #pragma unroll
            for (int m = 0; m < 8; m++){
                mma_tf32(sacc[nt], qf[2*m],   __float_as_uint(kf[m].x), __float_as_uint(kf[m].y));
                mma_tf32(sacc[nt], qf[2*m+1], __float_as_uint(kf[m].z), __float_as_uint(kf[m].w));
            }
        }

        // ===== causal mask + row max =====
        const bool maskblk = (j*BN + BN) > qbase;
        float rmax0 = -1e30f, rmax1 = -1e30f;
        #pragma unroll
        for (int nt = 0; nt < 8; nt++){
            if (maskblk){
                int colb = j*BN + nt*8 + 2*c0;
                if (colb     > qrow0) sacc[nt][0] = -1e30f;
                if (colb + 1 > qrow0) sacc[nt][1] = -1e30f;
                if (colb     > qrow1) sacc[nt][2] = -1e30f;
                if (colb + 1 > qrow1) sacc[nt][3] = -1e30f;
            }
            rmax0 = fmaxf(rmax0, fmaxf(sacc[nt][0], sacc[nt][1]));
            rmax1 = fmaxf(rmax1, fmaxf(sacc[nt][2], sacc[nt][3]));
        }
        rmax0 = fmaxf(rmax0, __shfl_xor_sync(0xffffffffu, rmax0, 1));
        rmax0 = fmaxf(rmax0, __shfl_xor_sync(0xffffffffu, rmax0, 2));
        rmax1 = fmaxf(rmax1, __shfl_xor_sync(0xffffffffu, rmax1, 1));
        rmax1 = fmaxf(rmax1, __shfl_xor_sync(0xffffffffu, rmax1, 2));

        float m0n = fmaxf(m0, rmax0), m1n = fmaxf(m1, rmax1);
        float a0 = ex2f(m0 - m0n), a1 = ex2f(m1 - m1n);
        m0 = m0n; m1 = m1n;

        // ===== P = exp2(S - m): store tf32 grouped; row sums =====
        float* Pw = Ps + warp*16*RSP;
        const int e0 = ((2*c0)   & 3)*20 + (c0>>1);
        const int e1 = ((2*c0+1) & 3)*20 + (c0>>1);
        float rs0 = 0.f, rs1 = 0.f;
        #pragma unroll
        for (int nt = 0; nt < 8; nt++){
            float p0 = ex2f(sacc[nt][0] - m0n);
            float p1 = ex2f(sacc[nt][1] - m0n);
            float p2 = ex2f(sacc[nt][2] - m1n);
            float p3 = ex2f(sacc[nt][3] - m1n);
            rs0 += p0 + p1; rs1 += p2 + p3;
            Pw[ r0   *RSP + e0 + 2*nt] = f2tff(p0);
            Pw[ r0   *RSP + e1 + 2*nt] = f2tff(p1);
            Pw[(r0+8)*RSP + e0 + 2*nt] = f2tff(p2);
            Pw[(r0+8)*RSP + e1 + 2*nt] = f2tff(p3);
        }
        rs0 += __shfl_xor_sync(0xffffffffu, rs0, 1);
        rs0 += __shfl_xor_sync(0xffffffffu, rs0, 2);
        rs1 += __shfl_xor_sync(0xffffffffu, rs1, 1);
        rs1 += __shfl_xor_sync(0xffffffffu, rs1, 2);
        l0 = l0*a0 + rs0;
        l1 = l1*a1 + rs1;

        #pragma unroll
        for (int nt = 0; nt < 16; nt++){
            o[nt][0] *= a0; o[nt][1] *= a0; o[nt][2] *= a1; o[nt][3] *= a1;
        }

        __syncwarp();   // P region is warp-private

        // ===== O += P * V =====
        unsigned pa[8][4];
        {
            const float4* p0 = (const float4*)(Pw +  r0   *RSP + c0*20);
            const float4* p8 = (const float4*)(Pw + (r0+8)*RSP + c0*20);
            #pragma unroll
            for (int m = 0; m < 4; m++){
                float4 f0 = p0[m], f8 = p8[m];
                pa[2*m  ][0] = __float_as_uint(f0.x); pa[2*m  ][1] = __float_as_uint(f8.x);
                pa[2*m  ][2] = __float_as_uint(f0.y); pa[2*m  ][3] = __float_as_uint(f8.y);
                pa[2*m+1][0] = __float_as_uint(f0.z); pa[2*m+1][1] = __float_as_uint(f8.z);
                pa[2*m+1][2] = __float_as_uint(f0.w); pa[2*m+1][3] = __float_as_uint(f8.w);
            }
        }
        #pragma unroll
        for (int nt = 0; nt < 16; nt++){
            const float4* vp = (const float4*)(Vb + (8*nt + r0)*RSV + c0*20);
            float4 vf[4];
            #pragma unroll
            for (int m = 0; m < 4; m++) vf[m] = vp[m];
            #pragma unroll
            for (int m = 0; m < 4; m++){
                mma_tf32(o[nt], pa[2*m],   __float_as_uint(vf[m].x), __float_as_uint(vf[m].y));
                mma_tf32(o[nt], pa[2*m+1], __float_as_uint(vf[m].z), __float_as_uint(vf[m].w));
            }
        }
        // no end barrier needed: next iter's top wait+sync fences buffer reuse
    }

    // ===== epilogue =====
    float inv0 = 1.f / l0, inv1 = 1.f / l1;
    const size_t ob = (size_t)b * SEQ * NUM_H * HD + (size_t)h * HD;
    #pragma unroll
    for (int nt = 0; nt < 16; nt++){
        int col = nt*8 + 2*c0;
        *(float2*)&Out[ob + (size_t)qrow0 * NUM_H * HD + col] =
            make_float2(o[nt][0]*inv0, o[nt][1]*inv0);
        *(float2*)&Out[ob + (size_t)qrow1 * NUM_H * HD + col] =
            make_float2(o[nt][2]*inv1, o[nt][3]*inv1);
    }
}

extern "C" void kernel_launch(void* const* d_in, const int* in_sizes, int n_in,
                              void* d_out, int out_size)
{
    const float* Q = (const float*)d_in[0];
    const float* K = (const float*)d_in[1];
    const float* V = (const float*)d_in[2];
    float* Out = (float*)d_out;

    cudaFuncSetAttribute(fa_fwd, cudaFuncAttributeMaxDynamicSharedMemorySize, SMEM_BYTES);

    dim3 grid(SEQ / BM, NUM_H, NUM_B);
    dim3 block(NTHREADS);
    fa_fwd<<<grid, block, SMEM_BYTES>>>(Q, K, V, Out);
}

// round 7
// speedup vs baseline: 1.4245x; 1.4245x over previous
#include <cuda_runtime.h>

#define NUM_B 2
#define NUM_H 32
#define SEQ   2048
#define HD    128
#define BM    128
#define BN    64
#define NTHREADS 256
#define KSTR  132   // K smem row stride (floats): conflict-free for K B-frag pattern
#define VSTR  136   // V smem row stride: conflict-free for V B-frag pattern
#define PSTR  76    // P smem row stride: conflict-free for P A-frag pattern
#define SMEM_FLOATS (2*BN*KSTR + 2*BN*VSTR + BM*PSTR)
#define SMEM_BYTES  (SMEM_FLOATS*4)

__device__ __forceinline__ unsigned f2tf(float x){
    unsigned r; asm("cvt.rna.tf32.f32 %0, %1;" : "=r"(r) : "f"(x)); return r;
}
__device__ __forceinline__ float ex2f(float x){
    float r; asm("ex2.approx.f32 %0, %1;" : "=f"(r) : "f"(x)); return r;
}
__device__ __forceinline__ void mma_tf32(float c[4], const unsigned a[4],
                                         unsigned b0, unsigned b1){
    asm volatile("mma.sync.aligned.m16n8k8.row.col.f32.tf32.tf32.f32 "
                 "{%0,%1,%2,%3},{%4,%5,%6,%7},{%8,%9},{%0,%1,%2,%3};"
                 : "+f"(c[0]),"+f"(c[1]),"+f"(c[2]),"+f"(c[3])
                 : "r"(a[0]),"r"(a[1]),"r"(a[2]),"r"(a[3]),"r"(b0),"r"(b1));
}

__global__ void __launch_bounds__(NTHREADS, 1)
fa_fwd(const float* __restrict__ Q, const float* __restrict__ K,
       const float* __restrict__ V, float* __restrict__ Out)
{
    extern __shared__ float sm_[];
    float* Ks = sm_;
    float* Vs = sm_ + 2*BN*KSTR;
    float* Ps = sm_ + 2*BN*KSTR + 2*BN*VSTR;

    const int tid  = threadIdx.x;
    const int warp = tid >> 5;
    const int lane = tid & 31;
    const int r0   = lane >> 2;
    const int c0   = lane & 3;

    const int qb = blockIdx.x, h = blockIdx.y, b = blockIdx.z;
    const int qbase = qb * BM;
    const size_t bh_off = ((size_t)b*NUM_H + h) * (size_t)SEQ * HD;
    const float* Qp = Q + bh_off;
    const float* Kp = K + bh_off;
    const float* Vp = V + bh_off;

    const unsigned ks_b = (unsigned)__cvta_generic_to_shared(Ks);
    const unsigned vs_b = (unsigned)__cvta_generic_to_shared(Vs);

    // 1/sqrt(128) * log2(e): layer-scaling cancels; softmax runs in exp2 domain
    const float SCALE2 = 0.08838834764831845f * 1.4426950408889634f;

    // ---- Q fragments in registers (RNA tf32, pre-scaled; loaded once) ----
    unsigned qf[16][4];
    const int qrow0 = qbase + warp*16 + r0;
    const int qrow1 = qrow0 + 8;
    #pragma unroll
    for (int kt = 0; kt < 16; kt++){
        int col = kt*8 + c0;
        qf[kt][0] = f2tf(Qp[(size_t)qrow0*HD + col]     * SCALE2);
        qf[kt][1] = f2tf(Qp[(size_t)qrow1*HD + col]     * SCALE2);
        qf[kt][2] = f2tf(Qp[(size_t)qrow0*HD + col + 4] * SCALE2);
        qf[kt][3] = f2tf(Qp[(size_t)qrow1*HD + col + 4] * SCALE2);
    }

    float o[16][4];
    #pragma unroll
    for (int i = 0; i < 16; i++){ o[i][0]=0.f; o[i][1]=0.f; o[i][2]=0.f; o[i][3]=0.f; }
    float m0 = -1e30f, m1 = -1e30f, l0 = 0.f, l1 = 0.f;

    const int jmax = 2*qb + 1;   // causal: key blocks 0..jmax

    auto load_tiles = [&](int j, int buf){
        const float* kg = Kp + (size_t)j*BN*HD;
        const float* vg = Vp + (size_t)j*BN*HD;
        #pragma unroll
        for (int i = 0; i < (BN*HD/4)/NTHREADS; i++){
            int idx = tid + i*NTHREADS;
            int row = idx >> 5;
            int c4  = (idx & 31) * 4;
            unsigned ka = ks_b + (unsigned)((buf*BN*KSTR + row*KSTR + c4) * 4);
            unsigned va = vs_b + (unsigned)((buf*BN*VSTR + row*VSTR + c4) * 4);
            asm volatile("cp.async.cg.shared.global [%0], [%1], 16;"
                         :: "r"(ka), "l"(kg + (size_t)row*HD + c4));
            asm volatile("cp.async.cg.shared.global [%0], [%1], 16;"
                         :: "r"(va), "l"(vg + (size_t)row*HD + c4));
        }
        asm volatile("cp.async.commit_group;");
    };

    load_tiles(0, 0);

    for (int j = 0; j <= jmax; j++){
        const int cur = j & 1;
        if (j < jmax){
            load_tiles(j + 1, cur ^ 1);          // prefetch next into other buffer
            asm volatile("cp.async.wait_group 1;");
        } else {
            asm volatile("cp.async.wait_group 0;");
        }
        __syncthreads();

        const float* Kb = Ks + cur*BN*KSTR;
        const float* Vb = Vs + cur*BN*VSTR;

        // ---- S = Q * K^T (warp computes 16x64); B fed raw fp32 (HW truncates to tf32) ----
        float sacc[8][4];
        #pragma unroll
        for (int i = 0; i < 8; i++){ sacc[i][0]=0.f; sacc[i][1]=0.f; sacc[i][2]=0.f; sacc[i][3]=0.f; }

        #pragma unroll
        for (int kt = 0; kt < 16; kt++){
            #pragma unroll
            for (int nt = 0; nt < 8; nt++){
                const float* kb = &Kb[(nt*8 + r0)*KSTR + kt*8 + c0];
                unsigned b0 = __float_as_uint(kb[0]);
                unsigned b1 = __float_as_uint(kb[4]);
                mma_tf32(sacc[nt], qf[kt], b0, b1);
            }
        }

        // ---- causal mask (diagonal block pair only) + row max ----
        const bool maskblk = (j*BN + BN) > qbase;
        float rmax0 = -1e30f, rmax1 = -1e30f;
        #pragma unroll
        for (int nt = 0; nt < 8; nt++){
            if (maskblk){
                int colb = j*BN + nt*8 + 2*c0;
                if (colb     > qrow0) sacc[nt][0] = -1e30f;
                if (colb + 1 > qrow0) sacc[nt][1] = -1e30f;
                if (colb     > qrow1) sacc[nt][2] = -1e30f;
                if (colb + 1 > qrow1) sacc[nt][3] = -1e30f;
            }
            rmax0 = fmaxf(rmax0, fmaxf(sacc[nt][0], sacc[nt][1]));
            rmax1 = fmaxf(rmax1, fmaxf(sacc[nt][2], sacc[nt][3]));
        }
        rmax0 = fmaxf(rmax0, __shfl_xor_sync(0xffffffffu, rmax0, 1));
        rmax0 = fmaxf(rmax0, __shfl_xor_sync(0xffffffffu, rmax0, 2));
        rmax1 = fmaxf(rmax1, __shfl_xor_sync(0xffffffffu, rmax1, 1));
        rmax1 = fmaxf(rmax1, __shfl_xor_sync(0xffffffffu, rmax1, 2));

        float m0n = fmaxf(m0, rmax0), m1n = fmaxf(m1, rmax1);
        float a0 = ex2f(m0 - m0n), a1 = ex2f(m1 - m1n);
        m0 = m0n; m1 = m1n;

        // ---- P = exp2(S - m) stored raw fp32; row-sums ----
        float* Pw = Ps + warp*16*PSTR;
        float rs0 = 0.f, rs1 = 0.f;
        #pragma unroll
        for (int nt = 0; nt < 8; nt++){
            float p0 = ex2f(sacc[nt][0] - m0n);
            float p1 = ex2f(sacc[nt][1] - m0n);
            float p2 = ex2f(sacc[nt][2] - m1n);
            float p3 = ex2f(sacc[nt][3] - m1n);
            rs0 += p0 + p1; rs1 += p2 + p3;
            *(float2*)&Pw[ r0     *PSTR + nt*8 + 2*c0] = make_float2(p0, p1);
            *(float2*)&Pw[(r0+8)  *PSTR + nt*8 + 2*c0] = make_float2(p2, p3);
        }
        rs0 += __shfl_xor_sync(0xffffffffu, rs0, 1);
        rs0 += __shfl_xor_sync(0xffffffffu, rs0, 2);
        rs1 += __shfl_xor_sync(0xffffffffu, rs1, 1);
        rs1 += __shfl_xor_sync(0xffffffffu, rs1, 2);
        l0 = l0*a0 + rs0;
        l1 = l1*a1 + rs1;

        #pragma unroll
        for (int nt = 0; nt < 16; nt++){
            o[nt][0] *= a0; o[nt][1] *= a0; o[nt][2] *= a1; o[nt][3] *= a1;
        }

        __syncwarp();   // P region is warp-private

        // ---- O += P * V; A and B fed raw fp32 (HW truncates) ----
        unsigned pa[8][4];
        #pragma unroll
        for (int kt = 0; kt < 8; kt++){
            pa[kt][0] = __float_as_uint(Pw[ r0    *PSTR + kt*8 + c0]);
            pa[kt][1] = __float_as_uint(Pw[(r0+8) *PSTR + kt*8 + c0]);
            pa[kt][2] = __float_as_uint(Pw[ r0    *PSTR + kt*8 + c0 + 4]);
            pa[kt][3] = __float_as_uint(Pw[(r0+8) *PSTR + kt*8 + c0 + 4]);
        }
        #pragma unroll
        for (int kt = 0; kt < 8; kt++){
            #pragma unroll
            for (int nt = 0; nt < 16; nt++){
                const float* vb = &Vb[(kt*8 + c0)*VSTR + nt*8 + r0];
                unsigned b0 = __float_as_uint(vb[0]);
                unsigned b1 = __float_as_uint(vb[4*VSTR]);
                mma_tf32(o[nt], pa[kt], b0, b1);
            }
        }
        __syncthreads();   // all warps done with this buffer before it's reloaded
    }

    // ---- epilogue: normalize + write [b, q, h*D] ----
    float inv0 = 1.f / l0, inv1 = 1.f / l1;
    const size_t ob = (size_t)b * SEQ * NUM_H * HD + (size_t)h * HD;
    #pragma unroll
    for (int nt = 0; nt < 16; nt++){
        int col = nt*8 + 2*c0;
        *(float2*)&Out[ob + (size_t)qrow0 * NUM_H * HD + col] =
            make_float2(o[nt][0]*inv0, o[nt][1]*inv0);
        *(float2*)&Out[ob + (size_t)qrow1 * NUM_H * HD + col] =
            make_float2(o[nt][2]*inv1, o[nt][3]*inv1);
    }
}

extern "C" void kernel_launch(void* const* d_in, const int* in_sizes, int n_in,
                              void* d_out, int out_size)
{
    const float* Q = (const float*)d_in[0];
    const float* K = (const float*)d_in[1];
    const float* V = (const float*)d_in[2];
    float* Out = (float*)d_out;

    cudaFuncSetAttribute(fa_fwd, cudaFuncAttributeMaxDynamicSharedMemorySize, SMEM_BYTES);

    dim3 grid(SEQ / BM, NUM_H, NUM_B);
    dim3 block(NTHREADS);
    fa_fwd<<<grid, block, SMEM_BYTES>>>(Q, K, V, Out);
}